// round 16
// baseline (speedup 1.0000x reference)
#include <cuda_runtime.h>

#define BATCH 64
#define SEQ   512
#define DIM   300
#define HID   600
#define G4    2400            // 4*HID
#define ROWS  (BATCH*SEQ)     // 32768

// fused-kernel config
#define GRID_F 148
#define NPERS  120            // persist blocks (60 per dir)
#define HALFG  60
#define NJ     10
#define NCOL   40
#define NT     480
#define KSPLIT 6
#define ZPAD   42
#define KC     120
#define NCHUNK 5
#define KSUB   20
#define CHUNKF (KC * 64)
#define CHUNKB (CHUNKF * 4)

// GEMM worker config
#define GBK    12
#define NTILE  25              // DIM / GBK
#define BN_W   120
#define NTW    20              // G4 / BN_W
#define NITEM  512             // 2 dirs * 64 b * 4 q
#define NJOB   (NITEM * NTW)

typedef unsigned long long u64;

// ---------------- packed f32x2 helpers ----------------
__device__ __forceinline__ void ffma2(u64& d, u64 a, u64 b) {
    asm("fma.rn.f32x2 %0, %1, %2, %0;" : "+l"(d) : "l"(a), "l"(b));
}
__device__ __forceinline__ u64 pack2(float lo, float hi) {
    u64 r; asm("mov.b64 %0, {%1, %2};" : "=l"(r) : "f"(lo), "f"(hi)); return r;
}
__device__ __forceinline__ void unpack2(u64 v, float& lo, float& hi) {
    asm("mov.b64 {%0, %1}, %2;" : "=f"(lo), "=f"(hi) : "l"(v));
}

// ---------------- fast gate math ----------------
__device__ __forceinline__ float fast_sigmoid(float x) {
    return __fdividef(1.f, 1.f + __expf(-x));
}
__device__ __forceinline__ float fast_tanh(float x) {
    float r; asm("tanh.approx.f32 %0, %1;" : "=f"(r) : "f"(x)); return r;
}

// ---------------- device scratch ----------------
__device__ float g_xw[(size_t)2 * ROWS * G4];
__device__ float g_UT[2 * G4 * HID];
__device__ float g_hT[2][2][HID][BATCH];
__device__ float g_hsum[2 * BATCH * HID];
__device__ unsigned g_flag[2][64][32];     // h producer flags
__device__ unsigned g_itemcnt[NITEM];      // xw item readiness counters (20 = ready)
__device__ int      g_order[NITEM];        // items sorted by need-step
__device__ unsigned g_jobctr;

// ---------------- init ----------------
__global__ void k_init() {
    int i = blockIdx.x * blockDim.x + threadIdx.x;
    float* p = &g_hT[0][0][0][0];
    if (i < 2 * 2 * HID * BATCH) p[i] = 0.f;
    if (i < 2 * 64 * 32) ((unsigned*)g_flag)[i] = 0u;
    if (i < NITEM) g_itemcnt[i] = 0u;
    if (i == 0) g_jobctr = 0u;
}

// ---------------- order items by need-step ----------------
__global__ void k_order(const int* __restrict__ lengths) {
    __shared__ int need[NITEM];
    int i = threadIdx.x;                   // 512 threads
    int dir = i >> 8, rem = i & 255, b = rem >> 2, q = rem & 3;
    int nd;
    if (dir == 0) {
        nd = (q == 0) ? 0 : 128 * q - 1;
    } else {
        int L = lengths[b];
        if (128 * q >= L) nd = SEQ + 1;    // never consumed -> last
        else { int t = L - 128 * (q + 1) - 1; nd = t < 0 ? 0 : t; }
    }
    need[i] = nd;
    __syncthreads();
    int rank = 0;
    for (int o = 0; o < NITEM; o++) {
        int no = need[o];
        if (no < nd || (no == nd && o < i)) rank++;
    }
    g_order[rank] = i;
}

// ---------------- transpose U -> UT ----------------
__global__ void k_transpose(const float* __restrict__ Uf, const float* __restrict__ Ub) {
    int i = blockIdx.x * blockDim.x + threadIdx.x;
    if (i >= HID * G4) return;
    int k = i / G4, n = i % G4;
    g_UT[n * HID + k]            = Uf[i];
    g_UT[G4 * HID + n * HID + k] = Ub[i];
}

// ---------------- xw prefetch with readiness poll (L2-coherent reads!) ----------
__device__ __forceinline__ void load_xw4p(float* px, int s, int b, int jj,
                                          int dir, int j0, int L, int& rq) {
    bool active = (dir == 0) ? (s < SEQ) : (s < L);
    if (!active) return;
    int trow = (dir == 0) ? s : (L - 1 - s);
    int q = trow >> 7;
    if (q != rq) {
        const unsigned* cp = &g_itemcnt[dir * 256 + b * 4 + q];
        unsigned v;
        do {
            asm volatile("ld.acquire.gpu.global.u32 %0, [%1];"
                         : "=r"(v) : "l"(cp) : "memory");
        } while (v < 20u);
        rq = q;
    }
    const float* xwr = g_xw + ((size_t)dir * ROWS + b * SEQ + trow) * G4 + (j0 + jj);
    // .cg (L2 coherence point): xw is produced CONCURRENTLY by worker blocks;
    // the .nc (__ldg) path is not coherent with those writes.
    px[0] = __ldcg(xwr);
    px[1] = __ldcg(xwr + HID);
    px[2] = __ldcg(xwr + 2 * HID);
    px[3] = __ldcg(xwr + 3 * HID);
}

// ---------------- gate math for one (b, jj) cell ----------------
__device__ __forceinline__ void gate_cell(const float* __restrict__ z_sh,
                                          const float* __restrict__ px,
                                          int b, int jj, int dir, int j0,
                                          int s, int L, int rp,
                                          float& cr, float& hs) {
    float z0 = 0.f, z1 = 0.f, z2 = 0.f, z3 = 0.f;
    #pragma unroll
    for (int p = 0; p < KSPLIT; p++) {
        const float* zb = z_sh + (p * 64 + b) * ZPAD;
        z0 += zb[jj];
        z1 += zb[NJ + jj];
        z2 += zb[2 * NJ + jj];
        z3 += zb[3 * NJ + jj];
    }
    bool active = (dir == 0) ? true : (s < L);
    if (!active) return;
    float ig = fast_sigmoid(z0 + px[0]);
    float fg = fast_sigmoid(z1 + px[1]);
    float gg = fast_tanh(z2 + px[2]);
    float og = fast_sigmoid(z3 + px[3]);
    cr = fg * cr + ig * gg;
    float h = og * fast_tanh(cr);
    __stcg(&g_hT[rp ^ 1][dir][j0 + jj][b], h);
    if (dir == 1 || s < L) hs += h;
}

// ---------------- poll h-producer flag, stage one 64B h slice ----------------
__device__ __forceinline__ void stage_chunk(unsigned h_base, const char* hsrc,
                                            int ck, int tid,
                                            const unsigned* flags, int myblk,
                                            unsigned tgt) {
    int prod = (ck * KC + (tid >> 2)) / NJ;
    if (prod != myblk) {
        const unsigned* fp = flags + prod * 32;
        unsigned v;
        do {
            asm volatile("ld.acquire.gpu.global.u32 %0, [%1];"
                         : "=r"(v) : "l"(fp) : "memory");
        } while (v < tgt);
    }
    unsigned dst = h_base + ((ck & 1) ? CHUNKB : 0) + tid * 64;
    const char* src = hsrc + (size_t)ck * CHUNKB + tid * 64;
    asm volatile("cp.async.cg.shared.global [%0], [%1], 16;" :: "r"(dst),      "l"(src));
    asm volatile("cp.async.cg.shared.global [%0], [%1], 16;" :: "r"(dst + 16), "l"(src + 16));
    asm volatile("cp.async.cg.shared.global [%0], [%1], 16;" :: "r"(dst + 32), "l"(src + 32));
    asm volatile("cp.async.cg.shared.global [%0], [%1], 16;" :: "r"(dst + 48), "l"(src + 48));
    asm volatile("cp.async.commit_group;" ::: "memory");
}

// ---------------- fused persistent kernel ----------------
__global__ __launch_bounds__(NT, 1) void k_fused(const int* __restrict__ lengths,
                                                 const float* __restrict__ X,
                                                 const float* __restrict__ Wf,
                                                 const float* __restrict__ bf,
                                                 const float* __restrict__ Wb,
                                                 const float* __restrict__ bb) {
    extern __shared__ __align__(16) float smem[];
    int tid = threadIdx.x;
    int bx  = blockIdx.x;

    if (bx >= NPERS) {
        // ============ GEMM worker path (28 blocks) ============
        float* As = smem;                              // [2][128][GBK]
        float* Bs = smem + 2 * 128 * GBK;              // [2][GBK][BN_W]
        int*  jslot = (int*)(smem + 2 * 128 * GBK + 2 * GBK * BN_W);
        unsigned asb = (unsigned)__cvta_generic_to_shared(As);
        unsigned bsb = (unsigned)__cvta_generic_to_shared(Bs);
        int tx = tid % 30, ty = tid / 30;              // 30 n-groups(4) x 16 m-groups(8)

        for (;;) {
            if (tid == 0) *jslot = (int)atomicAdd(&g_jobctr, 1u);
            __syncthreads();
            int j = *jslot;
            __syncthreads();
            if (j >= NJOB) break;
            int sit = j / NTW, nt = j % NTW;
            int item = g_order[sit];
            int dir = item >> 8, rem = item & 255, b = rem >> 2, q = rem & 3;
            int L = __ldg(&lengths[b]);
            if (dir == 1 && q * 128 >= L) continue;    // rows never consumed

            const float* W    = dir ? Wb : Wf;
            const float* bias = dir ? bb : bf;
            int m0 = b * SEQ + q * 128;                // X row base (dir-independent)
            int n0 = nt * BN_W;

            auto stage = [&](int t, int buf) {
                int k0 = t * GBK;
                if (tid < 128 * 3) {
                    int row = tid / 3, f4 = tid % 3;
                    unsigned dst = asb + (buf * 128 * GBK + row * GBK + f4 * 4) * 4;
                    const float* src = X + (size_t)(m0 + row) * DIM + k0 + f4 * 4;
                    asm volatile("cp.async.cg.shared.global [%0], [%1], 16;"
                                 :: "r"(dst), "l"(src));
                }
                if (tid < GBK * 30) {
                    int kk = tid / 30, c4 = tid % 30;
                    unsigned dst = bsb + (buf * GBK * BN_W + kk * BN_W + c4 * 4) * 4;
                    const float* src = W + (size_t)(k0 + kk) * G4 + n0 + c4 * 4;
                    asm volatile("cp.async.cg.shared.global [%0], [%1], 16;"
                                 :: "r"(dst), "l"(src));
                }
                asm volatile("cp.async.commit_group;" ::: "memory");
            };

            u64 acc[8][2] = {};
            stage(0, 0);
            for (int t = 0; t < NTILE; ++t) {
                int cur = t & 1;
                if (t + 1 < NTILE) {
                    stage(t + 1, cur ^ 1);
                    asm volatile("cp.async.wait_group 1;" ::: "memory");
                } else {
                    asm volatile("cp.async.wait_group 0;" ::: "memory");
                }
                __syncthreads();
                #pragma unroll
                for (int kk = 0; kk < GBK; ++kk) {
                    u64 bv0 = *(const u64*)&Bs[cur * GBK * BN_W + kk * BN_W + tx * 4];
                    u64 bv1 = *(const u64*)&Bs[cur * GBK * BN_W + kk * BN_W + tx * 4 + 2];
                    #pragma unroll
                    for (int i = 0; i < 8; ++i) {
                        float av = As[cur * 128 * GBK + (ty * 8 + i) * GBK + kk];
                        u64 ap = pack2(av, av);
                        ffma2(acc[i][0], ap, bv0);
                        ffma2(acc[i][1], ap, bv1);
                    }
                }
                __syncthreads();
            }

            float bv[4];
            #pragma unroll
            for (int jj = 0; jj < 4; ++jj) bv[jj] = __ldg(&bias[n0 + tx * 4 + jj]);
            float* outp = g_xw + (size_t)dir * ROWS * G4;
            #pragma unroll
            for (int i = 0; i < 8; ++i) {
                int row = m0 + ty * 8 + i;
                float2* o = (float2*)(outp + (size_t)row * G4 + n0 + tx * 4);
                float lo, hi;
                unpack2(acc[i][0], lo, hi);
                o[0] = make_float2(lo + bv[0], hi + bv[1]);
                unpack2(acc[i][1], lo, hi);
                o[1] = make_float2(lo + bv[2], hi + bv[3]);
            }

            __syncthreads();   // all STGs done before the release-add
            if (tid == 0) {
                unsigned old;
                asm volatile("atom.release.gpu.global.add.u32 %0, [%1], 1;"
                             : "=r"(old) : "l"(&g_itemcnt[item]) : "memory");
            }
        }
        return;
    }

    // ============ persist path (120 blocks) — R12 structure ============
    float* u_sh = smem;                            // [HID][NCOL]
    float* z_sh = smem + HID * NCOL;               // [KSPLIT][64][ZPAD]
    float* h_sh = z_sh + KSPLIT * 64 * ZPAD;       // [2][KC][64]

    int dir = (bx >= HALFG) ? 1 : 0;
    int blk = dir ? bx - HALFG : bx;
    int j0  = blk * NJ;

    unsigned h_base = (unsigned)__cvta_generic_to_shared(h_sh);
    const unsigned* flags = &g_flag[dir][0][0];

    {
        const float* UT = g_UT + (size_t)dir * G4 * HID;
        for (int idx = tid; idx < NCOL * HID; idx += NT) {
            int c = idx / HID, k = idx % HID;
            int gcol = (c / NJ) * HID + j0 + (c % NJ);
            u_sh[k * NCOL + c] = UT[(size_t)gcol * HID + k];
        }
    }

    int kh  = tid / 80;
    int r   = tid % 80;
    int bgr = (r / 10) * 8;     // b-group base
    int cc  = (r % 10) * 4;

    int b0c  = tid & 63;
    int jj0c = tid >> 6;
    int b1c  = (tid + NT) & 63;
    int jj1c = (tid + NT) >> 6;
    int L0 = __ldg(&lengths[b0c]);
    int L1 = (tid < 160) ? __ldg(&lengths[b1c]) : 0;
    float cr0 = 0.f, cr1 = 0.f, hs0 = 0.f, hs1 = 0.f;
    int rq0 = -1, rq1 = -1;

    float px0[4], px1[4], nx0[4], nx1[4];
    load_xw4p(px0, 0, b0c, jj0c, dir, j0, L0, rq0);
    if (tid < 160) load_xw4p(px1, 0, b1c, jj1c, dir, j0, L1, rq1);

    __syncthreads();

    for (int s = 0; s < SEQ; s++) {
        int rp = s & 1;
        const char* hsrc = (const char*)(&g_hT[rp][dir][0][0]);
        unsigned tgt = (unsigned)s;

        stage_chunk(h_base, hsrc, 0, tid, flags, blk, tgt);
        asm volatile("cp.async.wait_group 0;" ::: "memory");
        __syncthreads();

        u64 acc2[4][4] = {};
        #pragma unroll
        for (int ck = 0; ck < NCHUNK; ck++) {
            if (ck < NCHUNK - 1)
                stage_chunk(h_base, hsrc, ck + 1, tid, flags, blk, tgt);

            const float* hp = h_sh + ((ck & 1) ? CHUNKF : 0) + (kh * KSUB) * 64 + bgr;
            const float* up = u_sh + (ck * KC + kh * KSUB) * NCOL + cc;
            #pragma unroll 5
            for (int kk = 0; kk < KSUB; kk++) {
                float4 ha = *(const float4*)hp;
                float4 hb = *(const float4*)(hp + 4);
                hp += 64;
                float4 u4 = *(const float4*)up;
                up += NCOL;
                u64 hpair[4] = {pack2(ha.x, ha.y), pack2(ha.z, ha.w),
                                pack2(hb.x, hb.y), pack2(hb.z, hb.w)};
                u64 ub[4] = {pack2(u4.x, u4.x), pack2(u4.y, u4.y),
                             pack2(u4.z, u4.z), pack2(u4.w, u4.w)};
                #pragma unroll
                for (int i = 0; i < 4; i++)
                    #pragma unroll
                    for (int j = 0; j < 4; j++)
                        ffma2(acc2[i][j], hpair[i], ub[j]);
            }

            if (ck == NCHUNK - 1) {
                #pragma unroll
                for (int i = 0; i < 4; i++) {
                    float* zr0 = z_sh + ((kh * 64) + bgr + 2 * i) * ZPAD + cc;
                    float* zr1 = zr0 + ZPAD;
                    #pragma unroll
                    for (int j = 0; j < 4; j++) {
                        float lo, hi; unpack2(acc2[i][j], lo, hi);
                        zr0[j] = lo; zr1[j] = hi;
                    }
                }
                load_xw4p(nx0, s + 1, b0c, jj0c, dir, j0, L0, rq0);
                if (tid < 160) load_xw4p(nx1, s + 1, b1c, jj1c, dir, j0, L1, rq1);
            } else {
                asm volatile("cp.async.wait_group 0;" ::: "memory");
            }
            __syncthreads();
        }

        gate_cell(z_sh, px0, b0c, jj0c, dir, j0, s, L0, rp, cr0, hs0);
        if (tid < 160) gate_cell(z_sh, px1, b1c, jj1c, dir, j0, s, L1, rp, cr1, hs1);
        #pragma unroll
        for (int q = 0; q < 4; q++) { px0[q] = nx0[q]; px1[q] = nx1[q]; }
        __syncthreads();

        if (tid == 0) {
            asm volatile("st.release.gpu.global.u32 [%0], %1;"
                         :: "l"(&g_flag[dir][blk][0]), "r"((unsigned)(s + 1)) : "memory");
        }
    }

    g_hsum[dir * BATCH * HID + b0c * HID + j0 + jj0c] = hs0;
    if (tid < 160)
        g_hsum[dir * BATCH * HID + b1c * HID + j0 + jj1c] = hs1;
}

// ---------------- finalize: mean over T ----------------
__global__ void k_final(float* __restrict__ out) {
    int i = blockIdx.x * blockDim.x + threadIdx.x;
    if (i >= BATCH * 2 * HID) return;
    int b = i / (2 * HID), j = i % (2 * HID);
    float v = (j < HID) ? g_hsum[b * HID + j]
                        : g_hsum[BATCH * HID + b * HID + (j - HID)];
    out[i] = v * (1.0f / SEQ);
}

// ---------------- launch ----------------
extern "C" void kernel_launch(void* const* d_in, const int* in_sizes, int n_in,
                              void* d_out, int out_size) {
    const float *X = nullptr, *Wf = nullptr, *Uf = nullptr, *bf = nullptr;
    const float *Wb = nullptr, *Ub = nullptr, *bb = nullptr;
    const int* lengths = nullptr;
    int cW = 0, cU = 0, cb = 0;
    for (int i = 0; i < n_in; i++) {
        int s = in_sizes[i];
        if      (s == BATCH * SEQ * DIM) X = (const float*)d_in[i];
        else if (s == BATCH)             lengths = (const int*)d_in[i];
        else if (s == DIM * G4)   { if (cW++ == 0) Wf = (const float*)d_in[i]; else Wb = (const float*)d_in[i]; }
        else if (s == HID * G4)   { if (cU++ == 0) Uf = (const float*)d_in[i]; else Ub = (const float*)d_in[i]; }
        else if (s == G4)         { if (cb++ == 0) bf = (const float*)d_in[i]; else bb = (const float*)d_in[i]; }
    }

    static const int smem_bytes =
        (HID * NCOL + KSPLIT * 64 * ZPAD + 2 * KC * 64) * 4;   // 221952
    cudaFuncSetAttribute(k_fused, cudaFuncAttributeMaxDynamicSharedMemorySize, smem_bytes);

    k_init<<<(2 * 2 * HID * BATCH + 255) / 256, 256>>>();
    k_order<<<1, NITEM>>>(lengths);
    k_transpose<<<(HID * G4 + 255) / 256, 256>>>(Uf, Ub);
    k_fused<<<GRID_F, NT, smem_bytes>>>(lengths, X, Wf, bf, Wb, bb);
    k_final<<<(BATCH * 2 * HID + 255) / 256, 256>>>((float*)d_out);
}

// round 17
// speedup vs baseline: 1.3465x; 1.3465x over previous
#include <cuda_runtime.h>

#define BATCH 64
#define SEQ   512
#define DIM   300
#define HID   600
#define G4    2400            // 4*HID
#define ROWS  (BATCH*SEQ)     // 32768

// fused-kernel config
#define GRID_F 148
#define NPERS  120            // persist blocks (60 per dir)
#define HALFG  60
#define NJ     10
#define NCOL   40
#define NT     480
#define KSPLIT 6
#define ZPAD   42
#define KC     120
#define NCHUNK 5
#define KSUB   20
#define CHUNKF (KC * 64)
#define CHUNKB (CHUNKF * 4)

// GEMM worker config
#define GBK    12
#define NTILE  25              // DIM / GBK
#define BN_W   120
#define NTW    20              // G4 / BN_W
#define NITEM  512             // 2 dirs * 64 b * 4 q
#define NJOB   (NITEM * NTW)   // 10240
#define NJOBA  4096            // queue A: first 40% (all blocks drain)

typedef unsigned long long u64;

// ---------------- packed f32x2 helpers ----------------
__device__ __forceinline__ void ffma2(u64& d, u64 a, u64 b) {
    asm("fma.rn.f32x2 %0, %1, %2, %0;" : "+l"(d) : "l"(a), "l"(b));
}
__device__ __forceinline__ u64 pack2(float lo, float hi) {
    u64 r; asm("mov.b64 %0, {%1, %2};" : "=l"(r) : "f"(lo), "f"(hi)); return r;
}
__device__ __forceinline__ void unpack2(u64 v, float& lo, float& hi) {
    asm("mov.b64 {%0, %1}, %2;" : "=f"(lo), "=f"(hi) : "l"(v));
}

// ---------------- fast gate math ----------------
__device__ __forceinline__ float fast_sigmoid(float x) {
    return __fdividef(1.f, 1.f + __expf(-x));
}
__device__ __forceinline__ float fast_tanh(float x) {
    float r; asm("tanh.approx.f32 %0, %1;" : "=f"(r) : "f"(x)); return r;
}

// ---------------- device scratch ----------------
__device__ float g_xw[(size_t)2 * ROWS * G4];
__device__ float g_UT[2 * G4 * HID];
__device__ float g_hT[2][2][HID][BATCH];
__device__ float g_hsum[2 * BATCH * HID];
__device__ unsigned g_flag[2][64][32];     // h producer flags
__device__ unsigned g_itemcnt[NITEM];      // xw item readiness (20 = ready)
__device__ int      g_order[NITEM];        // items sorted by need-step
__device__ unsigned g_ctrA;
__device__ unsigned g_ctrB;

// ---------------- init ----------------
__global__ void k_init() {
    int i = blockIdx.x * blockDim.x + threadIdx.x;
    float* p = &g_hT[0][0][0][0];
    if (i < 2 * 2 * HID * BATCH) p[i] = 0.f;
    if (i < 2 * 64 * 32) ((unsigned*)g_flag)[i] = 0u;
    if (i < NITEM) g_itemcnt[i] = 0u;
    if (i == 0) { g_ctrA = 0u; g_ctrB = (unsigned)NJOBA; }
}

// ---------------- order items by need-step ----------------
__global__ void k_order(const int* __restrict__ lengths) {
    __shared__ int need[NITEM];
    int i = threadIdx.x;                   // 512 threads
    int dir = i >> 8, rem = i & 255, b = rem >> 2, q = rem & 3;
    int nd;
    if (dir == 0) {
        nd = (q == 0) ? 0 : 128 * q - 1;
    } else {
        int L = lengths[b];
        if (128 * q >= L) nd = SEQ + 1;    // never consumed -> last
        else { int t = L - 128 * (q + 1) - 1; nd = t < 0 ? 0 : t; }
    }
    need[i] = nd;
    __syncthreads();
    int rank = 0;
    for (int o = 0; o < NITEM; o++) {
        int no = need[o];
        if (no < nd || (no == nd && o < i)) rank++;
    }
    g_order[rank] = i;
}

// ---------------- transpose U -> UT ----------------
__global__ void k_transpose(const float* __restrict__ Uf, const float* __restrict__ Ub) {
    int i = blockIdx.x * blockDim.x + threadIdx.x;
    if (i >= HID * G4) return;
    int k = i / G4, n = i % G4;
    g_UT[n * HID + k]            = Uf[i];
    g_UT[G4 * HID + n * HID + k] = Ub[i];
}

// ---------------- GEMM job drain (shared by persist phase-1 and workers) ----
__device__ void gemm_drain(float* smem, int tid, unsigned* ctr, int limit,
                           const int* __restrict__ lengths,
                           const float* __restrict__ X,
                           const float* __restrict__ Wf, const float* __restrict__ bf,
                           const float* __restrict__ Wb, const float* __restrict__ bb) {
    float* As = smem;                              // [2][128][GBK]
    float* Bs = smem + 2 * 128 * GBK;              // [2][GBK][BN_W]
    int*  jslot = (int*)(smem + 2 * 128 * GBK + 2 * GBK * BN_W);
    unsigned asb = (unsigned)__cvta_generic_to_shared(As);
    unsigned bsb = (unsigned)__cvta_generic_to_shared(Bs);
    int tx = tid % 30, ty = tid / 30;              // 30 n-groups(4) x 16 m-groups(8)

    for (;;) {
        if (tid == 0) *jslot = (int)atomicAdd(ctr, 1u);
        __syncthreads();
        int j = *jslot;
        __syncthreads();
        if (j >= limit) break;
        int sit = j / NTW, nt = j % NTW;
        int item = g_order[sit];
        int dir = item >> 8, rem = item & 255, b = rem >> 2, q = rem & 3;
        int L = __ldg(&lengths[b]);
        if (dir == 1 && q * 128 >= L) continue;    // rows never consumed

        const float* W    = dir ? Wb : Wf;
        const float* bias = dir ? bb : bf;
        int m0 = b * SEQ + q * 128;
        int n0 = nt * BN_W;

        auto stage = [&](int t, int buf) {
            int k0 = t * GBK;
            if (tid < 128 * 3) {
                int row = tid / 3, f4 = tid % 3;
                unsigned dst = asb + (buf * 128 * GBK + row * GBK + f4 * 4) * 4;
                const float* src = X + (size_t)(m0 + row) * DIM + k0 + f4 * 4;
                asm volatile("cp.async.cg.shared.global [%0], [%1], 16;"
                             :: "r"(dst), "l"(src));
            }
            if (tid < GBK * 30) {
                int kk = tid / 30, c4 = tid % 30;
                unsigned dst = bsb + (buf * GBK * BN_W + kk * BN_W + c4 * 4) * 4;
                const float* src = W + (size_t)(k0 + kk) * G4 + n0 + c4 * 4;
                asm volatile("cp.async.cg.shared.global [%0], [%1], 16;"
                             :: "r"(dst), "l"(src));
            }
            asm volatile("cp.async.commit_group;" ::: "memory");
        };

        u64 acc[8][2] = {};
        stage(0, 0);
        for (int t = 0; t < NTILE; ++t) {
            int cur = t & 1;
            if (t + 1 < NTILE) {
                stage(t + 1, cur ^ 1);
                asm volatile("cp.async.wait_group 1;" ::: "memory");
            } else {
                asm volatile("cp.async.wait_group 0;" ::: "memory");
            }
            __syncthreads();
            #pragma unroll
            for (int kk = 0; kk < GBK; ++kk) {
                u64 bv0 = *(const u64*)&Bs[cur * GBK * BN_W + kk * BN_W + tx * 4];
                u64 bv1 = *(const u64*)&Bs[cur * GBK * BN_W + kk * BN_W + tx * 4 + 2];
                #pragma unroll
                for (int i = 0; i < 8; ++i) {
                    float av = As[cur * 128 * GBK + (ty * 8 + i) * GBK + kk];
                    u64 ap = pack2(av, av);
                    ffma2(acc[i][0], ap, bv0);
                    ffma2(acc[i][1], ap, bv1);
                }
            }
            __syncthreads();
        }

        float bv[4];
        #pragma unroll
        for (int jj = 0; jj < 4; ++jj) bv[jj] = __ldg(&bias[n0 + tx * 4 + jj]);
        float* outp = g_xw + (size_t)dir * ROWS * G4;
        #pragma unroll
        for (int i = 0; i < 8; ++i) {
            int row = m0 + ty * 8 + i;
            float2* o = (float2*)(outp + (size_t)row * G4 + n0 + tx * 4);
            float lo, hi;
            unpack2(acc[i][0], lo, hi);
            o[0] = make_float2(lo + bv[0], hi + bv[1]);
            unpack2(acc[i][1], lo, hi);
            o[1] = make_float2(lo + bv[2], hi + bv[3]);
        }

        __syncthreads();   // all STGs done before the release-add
        if (tid == 0) {
            unsigned old;
            asm volatile("atom.release.gpu.global.add.u32 %0, [%1], 1;"
                         : "=r"(old) : "l"(&g_itemcnt[item]) : "memory");
        }
    }
}

// ---------------- xw prefetch with readiness poll (L2-coherent) ----------------
__device__ __forceinline__ void load_xw4p(float* px, int s, int b, int jj,
                                          int dir, int j0, int L, int& rq) {
    bool active = (dir == 0) ? (s < SEQ) : (s < L);
    if (!active) return;
    int trow = (dir == 0) ? s : (L - 1 - s);
    int q = trow >> 7;
    if (q != rq) {
        const unsigned* cp = &g_itemcnt[dir * 256 + b * 4 + q];
        unsigned v;
        do {
            asm volatile("ld.acquire.gpu.global.u32 %0, [%1];"
                         : "=r"(v) : "l"(cp) : "memory");
        } while (v < 20u);
        rq = q;
    }
    const float* xwr = g_xw + ((size_t)dir * ROWS + b * SEQ + trow) * G4 + (j0 + jj);
    px[0] = __ldcg(xwr);
    px[1] = __ldcg(xwr + HID);
    px[2] = __ldcg(xwr + 2 * HID);
    px[3] = __ldcg(xwr + 3 * HID);
}

// ---------------- gate math for one (b, jj) cell ----------------
__device__ __forceinline__ void gate_cell(const float* __restrict__ z_sh,
                                          const float* __restrict__ px,
                                          int b, int jj, int dir, int j0,
                                          int s, int L, int rp,
                                          float& cr, float& hs) {
    float z0 = 0.f, z1 = 0.f, z2 = 0.f, z3 = 0.f;
    #pragma unroll
    for (int p = 0; p < KSPLIT; p++) {
        const float* zb = z_sh + (p * 64 + b) * ZPAD;
        z0 += zb[jj];
        z1 += zb[NJ + jj];
        z2 += zb[2 * NJ + jj];
        z3 += zb[3 * NJ + jj];
    }
    bool active = (dir == 0) ? true : (s < L);
    if (!active) return;
    float ig = fast_sigmoid(z0 + px[0]);
    float fg = fast_sigmoid(z1 + px[1]);
    float gg = fast_tanh(z2 + px[2]);
    float og = fast_sigmoid(z3 + px[3]);
    cr = fg * cr + ig * gg;
    float h = og * fast_tanh(cr);
    __stcg(&g_hT[rp ^ 1][dir][j0 + jj][b], h);
    if (dir == 1 || s < L) hs += h;
}

// ---------------- poll h-producer flag, stage one 64B h slice ----------------
__device__ __forceinline__ void stage_chunk(unsigned h_base, const char* hsrc,
                                            int ck, int tid,
                                            const unsigned* flags, int myblk,
                                            unsigned tgt) {
    int prod = (ck * KC + (tid >> 2)) / NJ;
    if (prod != myblk) {
        const unsigned* fp = flags + prod * 32;
        unsigned v;
        do {
            asm volatile("ld.acquire.gpu.global.u32 %0, [%1];"
                         : "=r"(v) : "l"(fp) : "memory");
        } while (v < tgt);
    }
    unsigned dst = h_base + ((ck & 1) ? CHUNKB : 0) + tid * 64;
    const char* src = hsrc + (size_t)ck * CHUNKB + tid * 64;
    asm volatile("cp.async.cg.shared.global [%0], [%1], 16;" :: "r"(dst),      "l"(src));
    asm volatile("cp.async.cg.shared.global [%0], [%1], 16;" :: "r"(dst + 16), "l"(src + 16));
    asm volatile("cp.async.cg.shared.global [%0], [%1], 16;" :: "r"(dst + 32), "l"(src + 32));
    asm volatile("cp.async.cg.shared.global [%0], [%1], 16;" :: "r"(dst + 48), "l"(src + 48));
    asm volatile("cp.async.commit_group;" ::: "memory");
}

// ---------------- fused persistent kernel ----------------
__global__ __launch_bounds__(NT, 1) void k_fused(const int* __restrict__ lengths,
                                                 const float* __restrict__ X,
                                                 const float* __restrict__ Wf,
                                                 const float* __restrict__ bf,
                                                 const float* __restrict__ Wb,
                                                 const float* __restrict__ bb) {
    extern __shared__ __align__(16) float smem[];
    int tid = threadIdx.x;
    int bx  = blockIdx.x;

    if (bx >= NPERS) {
        // workers: drain queue A, then queue B
        gemm_drain(smem, tid, &g_ctrA, NJOBA, lengths, X, Wf, bf, Wb, bb);
        gemm_drain(smem, tid, &g_ctrB, NJOB,  lengths, X, Wf, bf, Wb, bb);
        return;
    }

    // persist blocks: phase 1 — help drain queue A (urgent xw items)
    gemm_drain(smem, tid, &g_ctrA, NJOBA, lengths, X, Wf, bf, Wb, bb);
    __syncthreads();

    // ============ phase 2: recurrence (R12 structure) ============
    float* u_sh = smem;                            // [HID][NCOL]
    float* z_sh = smem + HID * NCOL;               // [KSPLIT][64][ZPAD]
    float* h_sh = z_sh + KSPLIT * 64 * ZPAD;       // [2][KC][64]

    int dir = (bx >= HALFG) ? 1 : 0;
    int blk = dir ? bx - HALFG : bx;
    int j0  = blk * NJ;

    unsigned h_base = (unsigned)__cvta_generic_to_shared(h_sh);
    const unsigned* flags = &g_flag[dir][0][0];

    {
        const float* UT = g_UT + (size_t)dir * G4 * HID;
        for (int idx = tid; idx < NCOL * HID; idx += NT) {
            int c = idx / HID, k = idx % HID;
            int gcol = (c / NJ) * HID + j0 + (c % NJ);
            u_sh[k * NCOL + c] = UT[(size_t)gcol * HID + k];
        }
    }

    int kh  = tid / 80;
    int r   = tid % 80;
    int bgr = (r / 10) * 8;
    int cc  = (r % 10) * 4;

    int b0c  = tid & 63;
    int jj0c = tid >> 6;
    int b1c  = (tid + NT) & 63;
    int jj1c = (tid + NT) >> 6;
    int L0 = __ldg(&lengths[b0c]);
    int L1 = (tid < 160) ? __ldg(&lengths[b1c]) : 0;
    float cr0 = 0.f, cr1 = 0.f, hs0 = 0.f, hs1 = 0.f;
    int rq0 = -1, rq1 = -1;

    float px0[4], px1[4], nx0[4], nx1[4];
    load_xw4p(px0, 0, b0c, jj0c, dir, j0, L0, rq0);
    if (tid < 160) load_xw4p(px1, 0, b1c, jj1c, dir, j0, L1, rq1);

    __syncthreads();

    for (int s = 0; s < SEQ; s++) {
        int rp = s & 1;
        const char* hsrc = (const char*)(&g_hT[rp][dir][0][0]);
        unsigned tgt = (unsigned)s;

        stage_chunk(h_base, hsrc, 0, tid, flags, blk, tgt);
        asm volatile("cp.async.wait_group 0;" ::: "memory");
        __syncthreads();

        u64 acc2[4][4] = {};
        #pragma unroll
        for (int ck = 0; ck < NCHUNK; ck++) {
            if (ck < NCHUNK - 1)
                stage_chunk(h_base, hsrc, ck + 1, tid, flags, blk, tgt);

            const float* hp = h_sh + ((ck & 1) ? CHUNKF : 0) + (kh * KSUB) * 64 + bgr;
            const float* up = u_sh + (ck * KC + kh * KSUB) * NCOL + cc;
            #pragma unroll 5
            for (int kk = 0; kk < KSUB; kk++) {
                float4 ha = *(const float4*)hp;
                float4 hb = *(const float4*)(hp + 4);
                hp += 64;
                float4 u4 = *(const float4*)up;
                up += NCOL;
                u64 hpair[4] = {pack2(ha.x, ha.y), pack2(ha.z, ha.w),
                                pack2(hb.x, hb.y), pack2(hb.z, hb.w)};
                u64 ub[4] = {pack2(u4.x, u4.x), pack2(u4.y, u4.y),
                             pack2(u4.z, u4.z), pack2(u4.w, u4.w)};
                #pragma unroll
                for (int i = 0; i < 4; i++)
                    #pragma unroll
                    for (int j = 0; j < 4; j++)
                        ffma2(acc2[i][j], hpair[i], ub[j]);
            }

            if (ck == NCHUNK - 1) {
                #pragma unroll
                for (int i = 0; i < 4; i++) {
                    float* zr0 = z_sh + ((kh * 64) + bgr + 2 * i) * ZPAD + cc;
                    float* zr1 = zr0 + ZPAD;
                    #pragma unroll
                    for (int j = 0; j < 4; j++) {
                        float lo, hi; unpack2(acc2[i][j], lo, hi);
                        zr0[j] = lo; zr1[j] = hi;
                    }
                }
                load_xw4p(nx0, s + 1, b0c, jj0c, dir, j0, L0, rq0);
                if (tid < 160) load_xw4p(nx1, s + 1, b1c, jj1c, dir, j0, L1, rq1);
            } else {
                asm volatile("cp.async.wait_group 0;" ::: "memory");
            }
            __syncthreads();
        }

        gate_cell(z_sh, px0, b0c, jj0c, dir, j0, s, L0, rp, cr0, hs0);
        if (tid < 160) gate_cell(z_sh, px1, b1c, jj1c, dir, j0, s, L1, rp, cr1, hs1);
        #pragma unroll
        for (int q = 0; q < 4; q++) { px0[q] = nx0[q]; px1[q] = nx1[q]; }
        __syncthreads();

        if (tid == 0) {
            asm volatile("st.release.gpu.global.u32 [%0], %1;"
                         :: "l"(&g_flag[dir][blk][0]), "r"((unsigned)(s + 1)) : "memory");
        }
    }

    g_hsum[dir * BATCH * HID + b0c * HID + j0 + jj0c] = hs0;
    if (tid < 160)
        g_hsum[dir * BATCH * HID + b1c * HID + j0 + jj1c] = hs1;
}

// ---------------- finalize: mean over T ----------------
__global__ void k_final(float* __restrict__ out) {
    int i = blockIdx.x * blockDim.x + threadIdx.x;
    if (i >= BATCH * 2 * HID) return;
    int b = i / (2 * HID), j = i % (2 * HID);
    float v = (j < HID) ? g_hsum[b * HID + j]
                        : g_hsum[BATCH * HID + b * HID + (j - HID)];
    out[i] = v * (1.0f / SEQ);
}

// ---------------- launch ----------------
extern "C" void kernel_launch(void* const* d_in, const int* in_sizes, int n_in,
                              void* d_out, int out_size) {
    const float *X = nullptr, *Wf = nullptr, *Uf = nullptr, *bf = nullptr;
    const float *Wb = nullptr, *Ub = nullptr, *bb = nullptr;
    const int* lengths = nullptr;
    int cW = 0, cU = 0, cb = 0;
    for (int i = 0; i < n_in; i++) {
        int s = in_sizes[i];
        if      (s == BATCH * SEQ * DIM) X = (const float*)d_in[i];
        else if (s == BATCH)             lengths = (const int*)d_in[i];
        else if (s == DIM * G4)   { if (cW++ == 0) Wf = (const float*)d_in[i]; else Wb = (const float*)d_in[i]; }
        else if (s == HID * G4)   { if (cU++ == 0) Uf = (const float*)d_in[i]; else Ub = (const float*)d_in[i]; }
        else if (s == G4)         { if (cb++ == 0) bf = (const float*)d_in[i]; else bb = (const float*)d_in[i]; }
    }

    static const int smem_bytes =
        (HID * NCOL + KSPLIT * 64 * ZPAD + 2 * KC * 64) * 4;   // 221952
    cudaFuncSetAttribute(k_fused, cudaFuncAttributeMaxDynamicSharedMemorySize, smem_bytes);

    k_init<<<(2 * 2 * HID * BATCH + 255) / 256, 256>>>();
    k_order<<<1, NITEM>>>(lengths);
    k_transpose<<<(HID * G4 + 255) / 256, 256>>>(Uf, Ub);
    k_fused<<<GRID_F, NT, smem_bytes>>>(lengths, X, Wf, bf, Wb, bb);
    k_final<<<(BATCH * 2 * HID + 255) / 256, 256>>>((float*)d_out);
}